// round 1
// baseline (speedup 1.0000x reference)
#include <cuda_runtime.h>
#include <math.h>

// ---------------------------------------------------------------------------
// LocalAttention (Swin-style windowed MHA)
//   B=8, DIM=512, H=W=128, WIN=8 -> 2048 windows x 64 tokens, HEADS=16, hd=32
// Pipeline:
//   gather(xa) -> Xa[131072,512]
//   gather(xb) -> Xb[131072,512]
//   Q  = (Xa @ Wq^T  + bq) * scale        [131072,512]
//   KV =  Xb @ Wkv^T + bkv                [131072,1024]
//   per (window,head): softmax(QK^T + bias) V -> AO[131072,512]
//   OW =  AO @ Wo^T + bo                  [131072,512]
//   scatter(OW) -> out[B,512,128,128]
// ---------------------------------------------------------------------------

#define TOK        131072
#define NWIN       2048
#define CDIM       512
#define NHEADS     16
#define HDIM       32

// scratch regions (float offsets). AO aliases XA, OW aliases XB (safe: XA/XB
// are dead after the Q/KV GEMMs complete, stream-ordered).
#define OFF_XA 0ull
#define OFF_XB 67108864ull
#define OFF_Q  134217728ull
#define OFF_KV 201326592ull
#define OFF_AO OFF_XA
#define OFF_OW OFF_XB

__device__ float g_scratch[335544320]; // 1.28 GiB

// ---------------------------------------------------------------------------
// gather: [B,C,H,W] -> token-major [TOK, 512].
// block = (c-chunk of 32, b*128+h image row). smem transpose, both sides coalesced.
// ---------------------------------------------------------------------------
__global__ __launch_bounds__(256) void gather_win(const float* __restrict__ src,
                                                  size_t dstOff)
{
    __shared__ float tile[32][129];
    float* dst = g_scratch + dstOff;
    int bh = blockIdx.y;
    int b = bh >> 7, h = bh & 127;
    int c0 = blockIdx.x << 5;
    int tid = threadIdx.x;

    const float* srow = src + ((size_t)(b * 512 + c0) * 128 + h) * 128;
#pragma unroll
    for (int it = 0; it < 16; it++) {
        int idx = tid + it * 256;
        int cc = idx >> 7, w = idx & 127;
        tile[cc][w] = srow[(size_t)cc * 16384 + w];
    }
    __syncthreads();
    int r1 = h >> 3, i = h & 7;
#pragma unroll
    for (int it = 0; it < 16; it++) {
        int idx = tid + it * 256;
        int w = idx >> 5, cc = idx & 31;
        int r2 = w >> 3, j = w & 7;
        int t = ((b * 256 + r1 * 16 + r2) << 6) + i * 8 + j;
        dst[(size_t)t * 512 + c0 + cc] = tile[cc][w];
    }
}

// ---------------------------------------------------------------------------
// scatter: token-major [TOK,512] -> [B,C,H,W] (writes d_out)
// ---------------------------------------------------------------------------
__global__ __launch_bounds__(256) void scatter_win(size_t srcOff,
                                                   float* __restrict__ dst)
{
    __shared__ float tile[32][129];
    const float* srcw = g_scratch + srcOff;
    int bh = blockIdx.y;
    int b = bh >> 7, h = bh & 127;
    int c0 = blockIdx.x << 5;
    int tid = threadIdx.x;
    int r1 = h >> 3, i = h & 7;

#pragma unroll
    for (int it = 0; it < 16; it++) {
        int idx = tid + it * 256;
        int w = idx >> 5, cc = idx & 31;
        int r2 = w >> 3, j = w & 7;
        int t = ((b * 256 + r1 * 16 + r2) << 6) + i * 8 + j;
        tile[cc][w] = srcw[(size_t)t * 512 + c0 + cc];
    }
    __syncthreads();
    float* drow = dst + ((size_t)(b * 512 + c0) * 128 + h) * 128;
#pragma unroll
    for (int it = 0; it < 16; it++) {
        int idx = tid + it * 256;
        int cc = idx >> 7, w = idx & 127;
        drow[(size_t)cc * 16384 + w] = tile[cc][w];
    }
}

// ---------------------------------------------------------------------------
// SGEMM: C[M,No] = (A[M,512] @ B[No,512]^T + bias) * scale
// 128x64 block tile, BK=16, 256 threads, 8x4 per-thread register tile.
// ---------------------------------------------------------------------------
__global__ __launch_bounds__(256) void sgemm_bias(size_t aOff,
                                                  const float* __restrict__ B,
                                                  const float* __restrict__ bias,
                                                  size_t cOff,
                                                  int No, float scale)
{
    __shared__ float As[16][128];
    __shared__ float Bs[16][64];
    const float* A = g_scratch + aOff;
    float* C = g_scratch + cOff;

    int tid = threadIdx.x;
    int n0 = blockIdx.x * 64;
    int m0 = blockIdx.y * 128;
    int tx = tid & 15, ty = tid >> 4;

    float acc[8][4];
#pragma unroll
    for (int u = 0; u < 8; u++)
#pragma unroll
        for (int v = 0; v < 4; v++) acc[u][v] = 0.f;

    const float* Ap = A + (size_t)m0 * 512;
    const float* Bp = B + (size_t)n0 * 512;

    for (int k0 = 0; k0 < 512; k0 += 16) {
#pragma unroll
        for (int r = 0; r < 2; r++) {
            int idx = tid + r * 256;
            int row = idx >> 2;
            int kq = (idx & 3) << 2;
            float4 va = *(const float4*)(Ap + (size_t)row * 512 + k0 + kq);
            As[kq + 0][row] = va.x;
            As[kq + 1][row] = va.y;
            As[kq + 2][row] = va.z;
            As[kq + 3][row] = va.w;
        }
        {
            int row = tid >> 2;
            int kq = (tid & 3) << 2;
            float4 vb = *(const float4*)(Bp + (size_t)row * 512 + k0 + kq);
            Bs[kq + 0][row] = vb.x;
            Bs[kq + 1][row] = vb.y;
            Bs[kq + 2][row] = vb.z;
            Bs[kq + 3][row] = vb.w;
        }
        __syncthreads();
#pragma unroll
        for (int kk = 0; kk < 16; kk++) {
            float4 a0 = *(const float4*)&As[kk][ty * 8];
            float4 a1 = *(const float4*)&As[kk][ty * 8 + 4];
            float4 b0 = *(const float4*)&Bs[kk][tx * 4];
            float a[8] = {a0.x, a0.y, a0.z, a0.w, a1.x, a1.y, a1.z, a1.w};
            float bb[4] = {b0.x, b0.y, b0.z, b0.w};
#pragma unroll
            for (int u = 0; u < 8; u++)
#pragma unroll
                for (int v = 0; v < 4; v++) acc[u][v] += a[u] * bb[v];
        }
        __syncthreads();
    }

    float4 bv = *(const float4*)(bias + n0 + tx * 4);
#pragma unroll
    for (int u = 0; u < 8; u++) {
        float4 o;
        o.x = (acc[u][0] + bv.x) * scale;
        o.y = (acc[u][1] + bv.y) * scale;
        o.z = (acc[u][2] + bv.z) * scale;
        o.w = (acc[u][3] + bv.w) * scale;
        *(float4*)(C + (size_t)(m0 + ty * 8 + u) * No + n0 + tx * 4) = o;
    }
}

// ---------------------------------------------------------------------------
// attention: one block per (window m, head h). 256 threads.
//   S = q k^T + bias; softmax rows; out = S v
// ---------------------------------------------------------------------------
__global__ __launch_bounds__(256) void attn_kernel(const float* __restrict__ rpb,
                                                   const int* __restrict__ relidx)
{
    __shared__ float qs[64][33];
    __shared__ float ks[64][33];
    __shared__ float vs[64][33];
    __shared__ float ps[64][68];

    const float* Q  = g_scratch + OFF_Q;
    const float* KV = g_scratch + OFF_KV;
    float* AO       = g_scratch + OFF_AO;

    int m = blockIdx.x;
    int h = blockIdx.y;
    int tid = threadIdx.x;
    size_t tb = (size_t)m * 64;

#pragma unroll
    for (int it = 0; it < 8; it++) {
        int idx = tid + it * 256;
        int n = idx >> 5, d = idx & 31;
        qs[n][d] = Q[(tb + n) * 512 + h * 32 + d];
        ks[n][d] = KV[(tb + n) * 1024 + h * 32 + d];
        vs[n][d] = KV[(tb + n) * 1024 + 512 + h * 32 + d];
    }
    __syncthreads();

    // S = q k^T  (64x64), 4x4 per thread
    {
        int tx = tid & 15, ty = tid >> 4;
        float s[4][4];
#pragma unroll
        for (int u = 0; u < 4; u++)
#pragma unroll
            for (int v = 0; v < 4; v++) s[u][v] = 0.f;
#pragma unroll
        for (int d = 0; d < 32; d++) {
            float a[4], b[4];
#pragma unroll
            for (int u = 0; u < 4; u++) a[u] = qs[ty * 4 + u][d];
#pragma unroll
            for (int v = 0; v < 4; v++) b[v] = ks[tx * 4 + v][d];
#pragma unroll
            for (int u = 0; u < 4; u++)
#pragma unroll
                for (int v = 0; v < 4; v++) s[u][v] += a[u] * b[v];
        }
#pragma unroll
        for (int u = 0; u < 4; u++)
#pragma unroll
            for (int v = 0; v < 4; v++) {
                int mq = ty * 4 + u, nk = tx * 4 + v;
                int ri = relidx[mq * 64 + nk];
                ps[mq][nk] = s[u][v] + rpb[ri * NHEADS + h];
            }
    }
    __syncthreads();

    // softmax per row: 4 lanes per row
    {
        int g = tid & 3, row = tid >> 2;
        float mx = -1e30f;
        for (int c = g; c < 64; c += 4) mx = fmaxf(mx, ps[row][c]);
        mx = fmaxf(mx, __shfl_xor_sync(0xffffffffu, mx, 1));
        mx = fmaxf(mx, __shfl_xor_sync(0xffffffffu, mx, 2));
        float sum = 0.f;
        for (int c = g; c < 64; c += 4) {
            float e = __expf(ps[row][c] - mx);
            ps[row][c] = e;
            sum += e;
        }
        sum += __shfl_xor_sync(0xffffffffu, sum, 1);
        sum += __shfl_xor_sync(0xffffffffu, sum, 2);
        float inv = 1.f / sum;
        for (int c = g; c < 64; c += 4) ps[row][c] *= inv;
    }
    __syncthreads();

    // out = P v  (64x32), 2x4 per thread
    {
        int tx = tid & 7, ty = tid >> 3;
        float acc[2][4];
#pragma unroll
        for (int u = 0; u < 2; u++)
#pragma unroll
            for (int v = 0; v < 4; v++) acc[u][v] = 0.f;
#pragma unroll
        for (int nk = 0; nk < 64; nk++) {
            float p0 = ps[ty * 2 + 0][nk];
            float p1 = ps[ty * 2 + 1][nk];
#pragma unroll
            for (int v = 0; v < 4; v++) {
                float vv = vs[nk][tx * 4 + v];
                acc[0][v] += p0 * vv;
                acc[1][v] += p1 * vv;
            }
        }
#pragma unroll
        for (int u = 0; u < 2; u++)
#pragma unroll
            for (int v = 0; v < 4; v++)
                AO[(tb + ty * 2 + u) * 512 + h * 32 + tx * 4 + v] = acc[u][v];
    }
}

// ---------------------------------------------------------------------------
extern "C" void kernel_launch(void* const* d_in, const int* in_sizes, int n_in,
                              void* d_out, int out_size)
{
    const float* xa     = (const float*)d_in[0];
    const float* xb     = (const float*)d_in[1];
    const float* Wq     = (const float*)d_in[2];
    const float* bq     = (const float*)d_in[3];
    const float* Wkv    = (const float*)d_in[4];
    const float* bkv    = (const float*)d_in[5];
    const float* Wo     = (const float*)d_in[6];
    const float* bo     = (const float*)d_in[7];
    const float* rpb    = (const float*)d_in[8];
    const int*   relidx = (const int*)d_in[9];
    float* out = (float*)d_out;

    const float scale = 0.17677669529663687f; // 32^-0.5

    dim3 gwin(16, 1024);   // 16 c-chunks x (B*H)
    gather_win<<<gwin, 256>>>(xa, OFF_XA);
    gather_win<<<gwin, 256>>>(xb, OFF_XB);

    sgemm_bias<<<dim3(8, 1024), 256>>>(OFF_XA, Wq, bq, OFF_Q, 512, scale);
    sgemm_bias<<<dim3(16, 1024), 256>>>(OFF_XB, Wkv, bkv, OFF_KV, 1024, 1.0f);

    attn_kernel<<<dim3(NWIN, NHEADS), 256>>>(rpb, relidx);

    sgemm_bias<<<dim3(8, 1024), 256>>>(OFF_AO, Wo, bo, OFF_OW, 512, 1.0f);

    scatter_win<<<gwin, 256>>>(OFF_OW, out);
}

// round 5
// speedup vs baseline: 2.2309x; 2.2309x over previous
#include <cuda_runtime.h>
#include <cuda_bf16.h>
#include <cstdint>
#include <math.h>

// ===========================================================================
// LocalAttention: tcgen05 bf16x3-split GEMMs + fp32 attention
//   B=8, DIM=512, H=W=128, WIN=8 -> 2048 windows x 64 tokens, HEADS=16, hd=32
//
// NOTE on targets: the harness build includes a plain compute_103 pass in
// addition to sm_103a. tcgen05.* is only legal on the 'a' feature target, so
// every tcgen05 use is guarded by __CUDA_ARCH_FEAT_SM103_ALL with a correct
// FFMA fallback for the non-'a' pass. On GB300 the sm_103a cubin runs.
// ===========================================================================

#if defined(__CUDA_ARCH_FEAT_SM103_ALL) || defined(__CUDA_ARCH_FEAT_SM100_ALL) || defined(__CUDA_ARCH_FEAT_SM101_ALL)
#define HAS_TCGEN05 1
#else
#define HAS_TCGEN05 0
#endif

#define TOK      131072
#define NWIN     2048
#define NHEADS   16

// ---- scratch regions (byte offsets) ----
#define OFF_XAH  0ull
#define OFF_XAL  134217728ull
#define OFF_XBH  268435456ull
#define OFF_XBL  402653184ull
#define OFF_Q    536870912ull      // fp32 [TOK,512]
#define OFF_KV   805306368ull      // fp32 [TOK,1024]
#define OFF_AOH  OFF_XAH           // aliases XA (dead after Q GEMM)
#define OFF_AOL  OFF_XAL
#define OFF_OW   OFF_XBH           // fp32 [TOK,512], aliases XB (dead after KV GEMM)
#define OFF_WQH  1342177280ull
#define OFF_WQL  1342701568ull
#define OFF_WKVH 1343225856ull
#define OFF_WKVL 1344274432ull
#define OFF_WOH  1345323008ull
#define OFF_WOL  1345847296ull
// end = 1346371584

__device__ __align__(1024) unsigned char g_scratch[1346371584ull];

// ===========================================================================
// PTX helpers (sm_103a)
// ===========================================================================
__device__ __forceinline__ uint32_t smem_u32(const void* p) {
    uint32_t a;
    asm("{ .reg .u64 t; cvta.to.shared.u64 t, %1; cvt.u32.u64 %0, t; }" : "=r"(a) : "l"(p));
    return a;
}
__device__ __forceinline__ uint32_t elect_one() {
    uint32_t pred;
    asm volatile("{\n\t.reg .pred p;\n\telect.sync _|p, 0xFFFFFFFF;\n\tselp.b32 %0, 1, 0, p;\n\t}" : "=r"(pred));
    return pred;
}
#define MBARRIER_INIT(addr, cnt) \
    asm volatile("mbarrier.init.shared.b64 [%0], %1;" :: "r"((uint32_t)(addr)), "r"((uint32_t)(cnt)) : "memory")
#define MBARRIER_INVAL(addr) \
    asm volatile("mbarrier.inval.shared.b64 [%0];" :: "r"((uint32_t)(addr)) : "memory")
#define MBARRIER_WAIT_PARITY(addr, par) do { \
    uint32_t _mb = (uint32_t)(addr); uint32_t _p = (uint32_t)(par); uint32_t _done; \
    asm volatile("{\n\t.reg .pred p;\n\t" \
        "mbarrier.try_wait.parity.acquire.cta.shared::cta.b64 p, [%1], %2;\n\t" \
        "selp.b32 %0, 1, 0, p;\n\t}" : "=r"(_done) : "r"(_mb), "r"(_p) : "memory"); \
    if (!_done) { \
        asm volatile("{\n\t.reg .pred P1;\n\t" \
            "WAIT_LOOP_%=:\n\t" \
            "mbarrier.try_wait.parity.acquire.cta.shared::cta.b64 P1, [%0], %1, 0x989680;\n\t" \
            "@P1 bra.uni WAIT_DONE_%=;\n\t" \
            "bra.uni WAIT_LOOP_%=;\n\t" \
            "WAIT_DONE_%=:\n\t}" :: "r"(_mb), "r"(_p) : "memory"); \
    } } while (0)
#define FENCE_ASYNC_SHARED()   asm volatile("fence.proxy.async.shared::cta;" ::: "memory")

#if HAS_TCGEN05
#define TCGEN05_ALLOC(sm, n) \
    asm volatile("tcgen05.alloc.cta_group::1.sync.aligned.shared::cta.b32 [%0], %1;" \
        :: "r"((uint32_t)(sm)), "r"((uint32_t)(n)) : "memory")
#define TCGEN05_DEALLOC(t, n) \
    asm volatile("tcgen05.dealloc.cta_group::1.sync.aligned.b32 %0, %1;" :: "r"(t), "r"((uint32_t)(n)))
#define TCGEN05_RELINQ() \
    asm volatile("tcgen05.relinquish_alloc_permit.cta_group::1.sync.aligned;")
#define TCGEN05_COMMIT(mb) \
    asm volatile("tcgen05.commit.cta_group::1.mbarrier::arrive::one.shared::cluster.b64 [%0];" \
        :: "r"((uint32_t)(mb)) : "memory")
#define TCGEN05_FENCE_AFTER()  asm volatile("tcgen05.fence::after_thread_sync;" ::: "memory")
#define TCGEN05_FENCE_BEFORE() asm volatile("tcgen05.fence::before_thread_sync;" ::: "memory")
#define TCGEN05_WAIT_LD()      asm volatile("tcgen05.wait::ld.sync.aligned;" ::: "memory")

#define TCGEN05_LD_X32(r, ta) \
    asm volatile("tcgen05.ld.sync.aligned.32x32b.x32.b32 " \
        "{%0, %1, %2, %3, %4, %5, %6, %7, " \
        " %8, %9, %10, %11, %12, %13, %14, %15, " \
        " %16, %17, %18, %19, %20, %21, %22, %23, " \
        " %24, %25, %26, %27, %28, %29, %30, %31}, [%32];" \
        : "=r"((r)[0]),  "=r"((r)[1]),  "=r"((r)[2]),  "=r"((r)[3]), \
          "=r"((r)[4]),  "=r"((r)[5]),  "=r"((r)[6]),  "=r"((r)[7]), \
          "=r"((r)[8]),  "=r"((r)[9]),  "=r"((r)[10]), "=r"((r)[11]), \
          "=r"((r)[12]), "=r"((r)[13]), "=r"((r)[14]), "=r"((r)[15]), \
          "=r"((r)[16]), "=r"((r)[17]), "=r"((r)[18]), "=r"((r)[19]), \
          "=r"((r)[20]), "=r"((r)[21]), "=r"((r)[22]), "=r"((r)[23]), \
          "=r"((r)[24]), "=r"((r)[25]), "=r"((r)[26]), "=r"((r)[27]), \
          "=r"((r)[28]), "=r"((r)[29]), "=r"((r)[30]), "=r"((r)[31]) \
        : "r"(ta))

__device__ __forceinline__ void mma_bf16_ss(uint32_t d, uint64_t ad, uint64_t bd,
                                            uint32_t idesc, uint32_t en) {
    asm volatile("{\n\t.reg .pred p;\n\tsetp.ne.u32 p, %5, 0;\n\t"
        "tcgen05.mma.cta_group::1.kind::f16 [%0], %1, %2, %3, {%4, %4, %4, %4}, p;\n\t}"
        :: "r"(d), "l"(ad), "l"(bd), "r"(idesc), "r"(0u), "r"(en) : "memory");
}
#endif // HAS_TCGEN05

// SW128 smem descriptor: layout=2 (SW128), version=1 (Blackwell), SBO=64, LBO=1
static constexpr uint64_t SMEM_DESC_BASE_SW128 =
    (uint64_t(2) << 61) | (uint64_t(1) << 46) | (uint64_t(64) << 32) | (uint64_t(1) << 16);
#define MAKE_SMEM_DESC(a) (SMEM_DESC_BASE_SW128 | ((uint64_t)((a) >> 4) & 0x3FFF))

__device__ __forceinline__ uint32_t sw128(uint32_t o) { return o ^ ((o >> 3) & 0x70); }

// kind::f16 SS MMA, cg1. D=fp32, A=B=bf16, M=128, N=128 (K=16 per step)
// bits: [4]=1 dtype F32, [7]=1 atype BF16, [10]=1 btype BF16,
//       [17:22]=N/8=16, [24:28]=M/16=8
static constexpr uint32_t GEMM_IDESC =
    (1u << 4) | (1u << 7) | (1u << 10) | ((128u / 8) << 17) | ((128u / 16) << 24);

// ===========================================================================
// prep_w: fp32 weight -> bf16 hi/lo
// ===========================================================================
__global__ __launch_bounds__(256) void prep_w(const float* __restrict__ w,
                                              size_t hiOff, size_t loOff, int n)
{
    __nv_bfloat16* hi = (__nv_bfloat16*)(g_scratch + hiOff);
    __nv_bfloat16* lo = (__nv_bfloat16*)(g_scratch + loOff);
    int i = blockIdx.x * 256 + threadIdx.x;
    if (i < n) {
        float x = w[i];
        __nv_bfloat16 h = __float2bfloat16(x);
        hi[i] = h;
        lo[i] = __float2bfloat16(x - __bfloat162float(h));
    }
}

// ===========================================================================
// gather_split: [B,C,H,W] fp32 -> token-major [TOK,512] bf16 hi/lo
// ===========================================================================
__global__ __launch_bounds__(256) void gather_split(const float* __restrict__ src,
                                                    size_t hiOff, size_t loOff)
{
    __shared__ float tile[32][129];
    __nv_bfloat16* dh = (__nv_bfloat16*)(g_scratch + hiOff);
    __nv_bfloat16* dl = (__nv_bfloat16*)(g_scratch + loOff);
    int bh = blockIdx.y;
    int b = bh >> 7, h = bh & 127;
    int c0 = blockIdx.x << 5;
    int tid = threadIdx.x;

    const float* srow = src + ((size_t)(b * 512 + c0) * 128 + h) * 128;
#pragma unroll
    for (int it = 0; it < 16; it++) {
        int idx = tid + it * 256;
        int cc = idx >> 7, w = idx & 127;
        tile[cc][w] = srow[(size_t)cc * 16384 + w];
    }
    __syncthreads();
    int r1 = h >> 3, i = h & 7;
#pragma unroll
    for (int it = 0; it < 16; it++) {
        int idx = tid + it * 256;
        int w = idx >> 5, cc = idx & 31;
        int r2 = w >> 3, j = w & 7;
        int t = ((b * 256 + r1 * 16 + r2) << 6) + i * 8 + j;
        float x = tile[cc][w];
        __nv_bfloat16 hv = __float2bfloat16(x);
        size_t o = (size_t)t * 512 + c0 + cc;
        dh[o] = hv;
        dl[o] = __float2bfloat16(x - __bfloat162float(hv));
    }
}

// ===========================================================================
// scatter: token-major fp32 [TOK,512] -> [B,C,H,W]
// ===========================================================================
__global__ __launch_bounds__(256) void scatter_win(float* __restrict__ dst)
{
    __shared__ float tile[32][129];
    const float* srcw = (const float*)(g_scratch + OFF_OW);
    int bh = blockIdx.y;
    int b = bh >> 7, h = bh & 127;
    int c0 = blockIdx.x << 5;
    int tid = threadIdx.x;
    int r1 = h >> 3, i = h & 7;

#pragma unroll
    for (int it = 0; it < 16; it++) {
        int idx = tid + it * 256;
        int w = idx >> 5, cc = idx & 31;
        int r2 = w >> 3, j = w & 7;
        int t = ((b * 256 + r1 * 16 + r2) << 6) + i * 8 + j;
        tile[cc][w] = srcw[(size_t)t * 512 + c0 + cc];
    }
    __syncthreads();
    float* drow = dst + ((size_t)(b * 512 + c0) * 128 + h) * 128;
#pragma unroll
    for (int it = 0; it < 16; it++) {
        int idx = tid + it * 256;
        int cc = idx >> 7, w = idx & 127;
        drow[(size_t)cc * 16384 + w] = tile[cc][w];
    }
}

// ===========================================================================
// gemm_bf16x3: C[M,No] = (Ahl[M,512] x Bhl[No,512]^T + bias) * scale
//   sm_103a: bf16 2-term split, 3 MMA passes, fp32 TMEM accumulate,
//            tile 128x256, BK=64 double-buffered, tcgen05 SS mode.
//   plain sm_103 pass: FFMA fallback (reconstructs fp32 = hi+lo).
// ===========================================================================
#define GEMM_SMEM 197632

__global__ __launch_bounds__(256) void gemm_bf16x3(
    size_t ahOff, size_t alOff, size_t bhOff, size_t blOff,
    const float* __restrict__ bias, size_t cOff, int No, float scale)
{
    extern __shared__ char smem[];
    const __nv_bfloat16* Ah = (const __nv_bfloat16*)(g_scratch + ahOff);
    const __nv_bfloat16* Al = (const __nv_bfloat16*)(g_scratch + alOff);
    const __nv_bfloat16* Bh = (const __nv_bfloat16*)(g_scratch + bhOff);
    const __nv_bfloat16* Bl = (const __nv_bfloat16*)(g_scratch + blOff);
    float* C = (float*)(g_scratch + cOff);

    int tid = threadIdx.x, wid = tid >> 5, lid = tid & 31;
    int n0 = blockIdx.x * 256, m0 = blockIdx.y * 128;

#if HAS_TCGEN05
    uint32_t sbase = smem_u32(smem);

    if (wid == 0) TCGEN05_ALLOC(sbase, 256);
    __syncthreads();
    uint32_t tmem;
    asm volatile("ld.shared.b32 %0, [%1];" : "=r"(tmem) : "r"(sbase));
    if (tid == 0) { MBARRIER_INIT(sbase + 16, 1); MBARRIER_INIT(sbase + 24, 1); }
    __syncthreads();

    for (int kb = 0; kb < 8; kb++) {
        int buf = kb & 1;
        uint32_t bo = 1024u + (uint32_t)buf * 98304u;
        if (kb >= 2) MBARRIER_WAIT_PARITY(sbase + 16 + 8 * buf, ((kb >> 1) - 1) & 1);

        int k0 = kb * 64;
        // A tiles: 128 rows x 64 bf16 (128B rows, SW128), hi+lo
        const uint4* gAh = (const uint4*)(Ah + (size_t)m0 * 512 + k0);
        const uint4* gAl = (const uint4*)(Al + (size_t)m0 * 512 + k0);
#pragma unroll
        for (int t = 0; t < 4; t++) {
            int idx = tid + t * 256;
            int r = idx >> 3, c = idx & 7;
            uint32_t so = sw128((uint32_t)(r * 128 + c * 16));
            *(uint4*)(smem + bo + so) = gAh[(size_t)r * 64 + c];
            *(uint4*)(smem + bo + 16384 + so) = gAl[(size_t)r * 64 + c];
        }
        // B tiles: 256 rows x 64 bf16, hi+lo
        const uint4* gBh = (const uint4*)(Bh + (size_t)n0 * 512 + k0);
        const uint4* gBl = (const uint4*)(Bl + (size_t)n0 * 512 + k0);
#pragma unroll
        for (int t = 0; t < 8; t++) {
            int idx = tid + t * 256;
            int r = idx >> 3, c = idx & 7;
            uint32_t so = sw128((uint32_t)(r * 128 + c * 16));
            *(uint4*)(smem + bo + 32768 + so) = gBh[(size_t)r * 64 + c];
            *(uint4*)(smem + bo + 65536 + so) = gBl[(size_t)r * 64 + c];
        }
        __syncthreads();

        if (wid == 0) {
            FENCE_ASYNC_SHARED();
            if (elect_one()) {
                uint64_t dA[2] = { MAKE_SMEM_DESC(sbase + bo),
                                   MAKE_SMEM_DESC(sbase + bo + 16384) };
                uint64_t dB[2] = { MAKE_SMEM_DESC(sbase + bo + 32768),
                                   MAKE_SMEM_DESC(sbase + bo + 65536) };
                const int pa[3] = {0, 1, 0}, pb[3] = {0, 0, 1};
#pragma unroll
                for (int p = 0; p < 3; p++) {
                    uint64_t ad = dA[pa[p]], bd = dB[pb[p]];
#pragma unroll
                    for (int ks = 0; ks < 4; ks++) {
                        uint32_t en = !(kb == 0 && p == 0 && ks == 0);
                        // two N=128 halves: B rows 0-127 / 128-255 (+16KB = +1024 desc units)
                        mma_bf16_ss(tmem, ad + ks * 2, bd + ks * 2, GEMM_IDESC, en);
                        mma_bf16_ss(tmem + 128, ad + ks * 2, bd + 1024 + ks * 2, GEMM_IDESC, en);
                    }
                }
                TCGEN05_COMMIT(sbase + 16 + 8 * buf);
            }
        }
    }

    // final wait: kb=7 commit = completion #4 of mbar[1]; in-loop wait at kb=7
    // consumed phase 0 (#3), so parity 1 here blocks for #4.
    MBARRIER_WAIT_PARITY(sbase + 24, 1);
    TCGEN05_FENCE_AFTER();

    // ---- epilogue: TMEM -> smem stage (coalesce) -> gmem ----
    float* stage = (float*)(smem + 1024);
    {
        int sp = wid & 3;             // subpartition rows sp*32 + lid
        int cbase = (wid >> 2) * 128; // warps 0-3: cols 0-127, 4-7: cols 128-255
#pragma unroll
        for (int cc = 0; cc < 128; cc += 32) {
            uint32_t r[32];
            TCGEN05_LD_X32(r, tmem + cbase + cc);
            TCGEN05_WAIT_LD();
            float* row = stage + (size_t)(sp * 32 + lid) * 260 + cbase + cc;
#pragma unroll
            for (int i = 0; i < 8; i++) {
                float4 v = make_float4(__uint_as_float(r[4 * i]), __uint_as_float(r[4 * i + 1]),
                                       __uint_as_float(r[4 * i + 2]), __uint_as_float(r[4 * i + 3]));
                *(float4*)(row + 4 * i) = v;
            }
        }
    }
    TCGEN05_FENCE_BEFORE();
    __syncthreads();

#pragma unroll
    for (int t = 0; t < 32; t++) {
        int j = tid + t * 256;        // float4 index in 128x256 tile
        int r = j >> 6, c4 = j & 63;
        float4 v = *(float4*)(stage + (size_t)r * 260 + c4 * 4);
        float4 b = *(const float4*)(bias + n0 + c4 * 4);
        float4 o;
        o.x = (v.x + b.x) * scale;
        o.y = (v.y + b.y) * scale;
        o.z = (v.z + b.z) * scale;
        o.w = (v.w + b.w) * scale;
        *(float4*)(C + (size_t)(m0 + r) * No + n0 + c4 * 4) = o;
    }

    __syncthreads();
    if (tid == 0) { MBARRIER_INVAL(sbase + 16); MBARRIER_INVAL(sbase + 24); }
    __syncthreads();
    if (wid == 0) { TCGEN05_RELINQ(); TCGEN05_DEALLOC(tmem, 256); }

#else  // ---- FFMA fallback for the plain compute_103 pass ----
    float* As = (float*)smem;                 // [16][128]
    float* Bs = (float*)(smem + 16 * 128 * 4); // [16][64]
    int tx = tid & 15, ty = tid >> 4;

    for (int nsub = 0; nsub < 4; nsub++) {
        int nc0 = n0 + nsub * 64;
        float acc[8][4];
#pragma unroll
        for (int u = 0; u < 8; u++)
#pragma unroll
            for (int v = 0; v < 4; v++) acc[u][v] = 0.f;

        for (int k0 = 0; k0 < 512; k0 += 16) {
#pragma unroll
            for (int t = 0; t < 8; t++) {
                int e = tid + t * 256;
                int r = e & 127, kk = e >> 7;
                size_t g = (size_t)(m0 + r) * 512 + k0 + kk;
                As[kk * 128 + r] = __bfloat162float(Ah[g]) + __bfloat162float(Al[g]);
            }
#pragma unroll
            for (int t = 0; t < 4; t++) {
                int e = tid + t * 256;
                int r = e & 63, kk = e >> 6;
                size_t g = (size_t)(nc0 + r) * 512 + k0 + kk;
                Bs[kk * 64 + r] = __bfloat162float(Bh[g]) + __bfloat162float(Bl[g]);
            }
            __syncthreads();
#pragma unroll
            for (int kk = 0; kk < 16; kk++) {
                float a[8], b[4];
#pragma unroll
                for (int u = 0; u < 8; u++) a[u] = As[kk * 128 + ty * 8 + u];
#pragma unroll
                for (int v = 0; v < 4; v++) b[v] = Bs[kk * 64 + tx * 4 + v];
#pragma unroll
                for (int u = 0; u < 8; u++)
#pragma unroll
                    for (int v = 0; v < 4; v++) acc[u][v] += a[u] * b[v];
            }
            __syncthreads();
        }

#pragma unroll
        for (int u = 0; u < 8; u++)
#pragma unroll
            for (int v = 0; v < 4; v++)
                C[(size_t)(m0 + ty * 8 + u) * No + nc0 + tx * 4 + v] =
                    (acc[u][v] + bias[nc0 + tx * 4 + v]) * scale;
        __syncthreads();
    }
#endif
}

// ===========================================================================
// attention: one block per (window, head); Q/KV fp32 in, AO bf16 hi/lo out
// ===========================================================================
__global__ __launch_bounds__(256) void attn_kernel(const float* __restrict__ rpb,
                                                   const int* __restrict__ relidx)
{
    __shared__ float qs[64][33];
    __shared__ float ks[64][33];
    __shared__ float vs[64][33];
    __shared__ float ps[64][68];

    const float* Q  = (const float*)(g_scratch + OFF_Q);
    const float* KV = (const float*)(g_scratch + OFF_KV);
    __nv_bfloat16* AOh = (__nv_bfloat16*)(g_scratch + OFF_AOH);
    __nv_bfloat16* AOl = (__nv_bfloat16*)(g_scratch + OFF_AOL);

    int m = blockIdx.x;
    int h = blockIdx.y;
    int tid = threadIdx.x;
    size_t tb = (size_t)m * 64;

#pragma unroll
    for (int it = 0; it < 8; it++) {
        int idx = tid + it * 256;
        int n = idx >> 5, d = idx & 31;
        qs[n][d] = Q[(tb + n) * 512 + h * 32 + d];
        ks[n][d] = KV[(tb + n) * 1024 + h * 32 + d];
        vs[n][d] = KV[(tb + n) * 1024 + 512 + h * 32 + d];
    }
    __syncthreads();

    {
        int tx = tid & 15, ty = tid >> 4;
        float s[4][4];
#pragma unroll
        for (int u = 0; u < 4; u++)
#pragma unroll
            for (int v = 0; v < 4; v++) s[u][v] = 0.f;
#pragma unroll
        for (int d = 0; d < 32; d++) {
            float a[4], b[4];
#pragma unroll
            for (int u = 0; u < 4; u++) a[u] = qs[ty * 4 + u][d];
#pragma unroll
            for (int v = 0; v < 4; v++) b[v] = ks[tx * 4 + v][d];
#pragma unroll
            for (int u = 0; u < 4; u++)
#pragma unroll
                for (int v = 0; v < 4; v++) s[u][v] += a[u] * b[v];
        }
#pragma unroll
        for (int u = 0; u < 4; u++)
#pragma unroll
            for (int v = 0; v < 4; v++) {
                int mq = ty * 4 + u, nk = tx * 4 + v;
                int ri = relidx[mq * 64 + nk];
                ps[mq][nk] = s[u][v] + rpb[ri * NHEADS + h];
            }
    }
    __syncthreads();

    {
        int g = tid & 3, row = tid >> 2;
        float mx = -1e30f;
        for (int c = g; c < 64; c += 4) mx = fmaxf(mx, ps[row][c]);
        mx = fmaxf(mx, __shfl_xor_sync(0xffffffffu, mx, 1));
        mx = fmaxf(mx, __shfl_xor_sync(0xffffffffu, mx, 2));
        float sum = 0.f;
        for (int c = g; c < 64; c += 4) {
            float e = __expf(ps[row][c] - mx);
            ps[row][c] = e;
            sum += e;
        }
        sum += __shfl_xor_sync(0xffffffffu, sum, 1);
        sum += __shfl_xor_sync(0xffffffffu, sum, 2);
        float inv = 1.f / sum;
        for (int c = g; c < 64; c += 4) ps[row][c] *= inv;
    }
    __syncthreads();

    {
        int tx = tid & 7, ty = tid >> 3;
        float acc[2][4];
#pragma unroll
        for (int u = 0; u < 2; u++)
#pragma unroll
            for (int v = 0; v < 4; v++) acc[u][v] = 0.f;
#pragma unroll
        for (int nk = 0; nk < 64; nk++) {
            float p0 = ps[ty * 2 + 0][nk];
            float p1 = ps[ty * 2 + 1][nk];
#pragma unroll
            for (int v = 0; v < 4; v++) {
                float vv = vs[nk][tx * 4 + v];
                acc[0][v] += p0 * vv;
                acc[1][v] += p1 * vv;
            }
        }
#pragma unroll
        for (int u = 0; u < 2; u++) {
            size_t o = (tb + ty * 2 + u) * 512 + h * 32 + tx * 4;
            unsigned short hh[4], ll[4];
#pragma unroll
            for (int v = 0; v < 4; v++) {
                float x = acc[u][v];
                __nv_bfloat16 hv = __float2bfloat16(x);
                __nv_bfloat16 lv = __float2bfloat16(x - __bfloat162float(hv));
                hh[v] = *(unsigned short*)&hv;
                ll[v] = *(unsigned short*)&lv;
            }
            uint2 ph = make_uint2((uint32_t)hh[0] | ((uint32_t)hh[1] << 16),
                                  (uint32_t)hh[2] | ((uint32_t)hh[3] << 16));
            uint2 pl = make_uint2((uint32_t)ll[0] | ((uint32_t)ll[1] << 16),
                                  (uint32_t)ll[2] | ((uint32_t)ll[3] << 16));
            *(uint2*)(AOh + o) = ph;
            *(uint2*)(AOl + o) = pl;
        }
    }
}

// ===========================================================================
extern "C" void kernel_launch(void* const* d_in, const int* in_sizes, int n_in,
                              void* d_out, int out_size)
{
    const float* xa     = (const float*)d_in[0];
    const float* xb     = (const float*)d_in[1];
    const float* Wq     = (const float*)d_in[2];
    const float* bq     = (const float*)d_in[3];
    const float* Wkv    = (const float*)d_in[4];
    const float* bkv    = (const float*)d_in[5];
    const float* Wo     = (const float*)d_in[6];
    const float* bo     = (const float*)d_in[7];
    const float* rpb    = (const float*)d_in[8];
    const int*   relidx = (const int*)d_in[9];
    float* out = (float*)d_out;

    const float scale = 0.17677669529663687f; // 32^-0.5

    // idempotent, non-enqueuing, capture-safe; called every time (no static guards)
    cudaFuncSetAttribute(gemm_bf16x3, cudaFuncAttributeMaxDynamicSharedMemorySize, GEMM_SMEM);

    prep_w<<<1024, 256>>>(Wq,  OFF_WQH,  OFF_WQL,  512 * 512);
    prep_w<<<2048, 256>>>(Wkv, OFF_WKVH, OFF_WKVL, 1024 * 512);
    prep_w<<<1024, 256>>>(Wo,  OFF_WOH,  OFF_WOL,  512 * 512);

    dim3 gwin(16, 1024);
    gather_split<<<gwin, 256>>>(xa, OFF_XAH, OFF_XAL);
    gather_split<<<gwin, 256>>>(xb, OFF_XBH, OFF_XBL);

    gemm_bf16x3<<<dim3(2, 1024), 256, GEMM_SMEM>>>(OFF_XAH, OFF_XAL, OFF_WQH, OFF_WQL,
                                                   bq, OFF_Q, 512, scale);
    gemm_bf16x3<<<dim3(4, 1024), 256, GEMM_SMEM>>>(OFF_XBH, OFF_XBL, OFF_WKVH, OFF_WKVL,
                                                   bkv, OFF_KV, 1024, 1.0f);

    attn_kernel<<<dim3(NWIN, NHEADS), 256>>>(rpb, relidx);

    gemm_bf16x3<<<dim3(2, 1024), 256, GEMM_SMEM>>>(OFF_AOH, OFF_AOL, OFF_WOH, OFF_WOL,
                                                   bo, OFF_OW, 512, 1.0f);

    scatter_win<<<gwin, 256>>>(out);
}

// round 6
// speedup vs baseline: 3.3143x; 1.4857x over previous
#include <cuda_runtime.h>
#include <cuda_bf16.h>
#include <cstdint>
#include <math.h>

// ===========================================================================
// LocalAttention: tcgen05 bf16x3-split GEMMs (256x256xBK32 tiles, SW64,
// depth-3 pipeline) + fp32 attention
//   B=8, DIM=512, H=W=128, WIN=8 -> 2048 windows x 64 tokens, HEADS=16, hd=32
//
// tcgen05.* is only legal on the 'a' feature target; plain compute_103 pass
// gets an FFMA fallback (never selected on GB300).
// ===========================================================================

#if defined(__CUDA_ARCH_FEAT_SM103_ALL) || defined(__CUDA_ARCH_FEAT_SM100_ALL) || defined(__CUDA_ARCH_FEAT_SM101_ALL)
#define HAS_TCGEN05 1
#else
#define HAS_TCGEN05 0
#endif

#define TOK      131072
#define NWIN     2048
#define NHEADS   16

// ---- scratch regions (byte offsets) ----
#define OFF_XAH  0ull
#define OFF_XAL  134217728ull
#define OFF_XBH  268435456ull
#define OFF_XBL  402653184ull
#define OFF_Q    536870912ull      // fp32 [TOK,512]
#define OFF_KV   805306368ull      // fp32 [TOK,1024]
#define OFF_AOH  OFF_XAH           // aliases XA (dead after Q GEMM)
#define OFF_AOL  OFF_XAL
#define OFF_OW   OFF_XBH           // fp32 [TOK,512], aliases XB (dead after KV GEMM)
#define OFF_WQH  1342177280ull
#define OFF_WQL  1342701568ull
#define OFF_WKVH 1343225856ull
#define OFF_WKVL 1344274432ull
#define OFF_WOH  1345323008ull
#define OFF_WOL  1345847296ull
// end = 1346371584

__device__ __align__(1024) unsigned char g_scratch[1346371584ull];

// ===========================================================================
// PTX helpers (sm_103a)
// ===========================================================================
__device__ __forceinline__ uint32_t smem_u32(const void* p) {
    uint32_t a;
    asm("{ .reg .u64 t; cvta.to.shared.u64 t, %1; cvt.u32.u64 %0, t; }" : "=r"(a) : "l"(p));
    return a;
}
__device__ __forceinline__ uint32_t elect_one() {
    uint32_t pred;
    asm volatile("{\n\t.reg .pred p;\n\telect.sync _|p, 0xFFFFFFFF;\n\tselp.b32 %0, 1, 0, p;\n\t}" : "=r"(pred));
    return pred;
}
#define MBARRIER_INIT(addr, cnt) \
    asm volatile("mbarrier.init.shared.b64 [%0], %1;" :: "r"((uint32_t)(addr)), "r"((uint32_t)(cnt)) : "memory")
#define MBARRIER_INVAL(addr) \
    asm volatile("mbarrier.inval.shared.b64 [%0];" :: "r"((uint32_t)(addr)) : "memory")
#define MBARRIER_WAIT_PARITY(addr, par) do { \
    uint32_t _mb = (uint32_t)(addr); uint32_t _p = (uint32_t)(par); uint32_t _done; \
    asm volatile("{\n\t.reg .pred p;\n\t" \
        "mbarrier.try_wait.parity.acquire.cta.shared::cta.b64 p, [%1], %2;\n\t" \
        "selp.b32 %0, 1, 0, p;\n\t}" : "=r"(_done) : "r"(_mb), "r"(_p) : "memory"); \
    if (!_done) { \
        asm volatile("{\n\t.reg .pred P1;\n\t" \
            "WAIT_LOOP_%=:\n\t" \
            "mbarrier.try_wait.parity.acquire.cta.shared::cta.b64 P1, [%0], %1, 0x989680;\n\t" \
            "@P1 bra.uni WAIT_DONE_%=;\n\t" \
            "bra.uni WAIT_LOOP_%=;\n\t" \
            "WAIT_DONE_%=:\n\t}" :: "r"(_mb), "r"(_p) : "memory"); \
    } } while (0)
#define FENCE_ASYNC_SHARED()   asm volatile("fence.proxy.async.shared::cta;" ::: "memory")

#if HAS_TCGEN05
#define TCGEN05_ALLOC(sm, n) \
    asm volatile("tcgen05.alloc.cta_group::1.sync.aligned.shared::cta.b32 [%0], %1;" \
        :: "r"((uint32_t)(sm)), "r"((uint32_t)(n)) : "memory")
#define TCGEN05_DEALLOC(t, n) \
    asm volatile("tcgen05.dealloc.cta_group::1.sync.aligned.b32 %0, %1;" :: "r"(t), "r"((uint32_t)(n)))
#define TCGEN05_RELINQ() \
    asm volatile("tcgen05.relinquish_alloc_permit.cta_group::1.sync.aligned;")
#define TCGEN05_COMMIT(mb) \
    asm volatile("tcgen05.commit.cta_group::1.mbarrier::arrive::one.shared::cluster.b64 [%0];" \
        :: "r"((uint32_t)(mb)) : "memory")
#define TCGEN05_FENCE_AFTER()  asm volatile("tcgen05.fence::after_thread_sync;" ::: "memory")
#define TCGEN05_FENCE_BEFORE() asm volatile("tcgen05.fence::before_thread_sync;" ::: "memory")
#define TCGEN05_WAIT_LD()      asm volatile("tcgen05.wait::ld.sync.aligned;" ::: "memory")

#define TCGEN05_LD_X32(r, ta) \
    asm volatile("tcgen05.ld.sync.aligned.32x32b.x32.b32 " \
        "{%0, %1, %2, %3, %4, %5, %6, %7, " \
        " %8, %9, %10, %11, %12, %13, %14, %15, " \
        " %16, %17, %18, %19, %20, %21, %22, %23, " \
        " %24, %25, %26, %27, %28, %29, %30, %31}, [%32];" \
        : "=r"((r)[0]),  "=r"((r)[1]),  "=r"((r)[2]),  "=r"((r)[3]), \
          "=r"((r)[4]),  "=r"((r)[5]),  "=r"((r)[6]),  "=r"((r)[7]), \
          "=r"((r)[8]),  "=r"((r)[9]),  "=r"((r)[10]), "=r"((r)[11]), \
          "=r"((r)[12]), "=r"((r)[13]), "=r"((r)[14]), "=r"((r)[15]), \
          "=r"((r)[16]), "=r"((r)[17]), "=r"((r)[18]), "=r"((r)[19]), \
          "=r"((r)[20]), "=r"((r)[21]), "=r"((r)[22]), "=r"((r)[23]), \
          "=r"((r)[24]), "=r"((r)[25]), "=r"((r)[26]), "=r"((r)[27]), \
          "=r"((r)[28]), "=r"((r)[29]), "=r"((r)[30]), "=r"((r)[31]) \
        : "r"(ta))

__device__ __forceinline__ void mma_bf16_ss(uint32_t d, uint64_t ad, uint64_t bd,
                                            uint32_t idesc, uint32_t en) {
    asm volatile("{\n\t.reg .pred p;\n\tsetp.ne.u32 p, %5, 0;\n\t"
        "tcgen05.mma.cta_group::1.kind::f16 [%0], %1, %2, %3, {%4, %4, %4, %4}, p;\n\t}"
        :: "r"(d), "l"(ad), "l"(bd), "r"(idesc), "r"(0u), "r"(en) : "memory");
}
#endif // HAS_TCGEN05

// SW64 smem descriptor: layout=4 (SW64), version=1 (Blackwell), SBO=32, LBO=1
// atom = 8 rows x 64 bytes; rows here are 64B (BK=32 bf16).
static constexpr uint64_t SMEM_DESC_BASE_SW64 =
    (uint64_t(4) << 61) | (uint64_t(1) << 46) | (uint64_t(32) << 32) | (uint64_t(1) << 16);
#define MAKE_SMEM_DESC64(a) (SMEM_DESC_BASE_SW64 | ((uint64_t)((a) >> 4) & 0x3FFF))

__device__ __forceinline__ uint32_t sw64(uint32_t o) { return o ^ ((o >> 3) & 0x30); }

// kind::f16 SS MMA, cg1. D=fp32, A=B=bf16, M=128, N=128 (K=16 per step)
static constexpr uint32_t GEMM_IDESC =
    (1u << 4) | (1u << 7) | (1u << 10) | ((128u / 8) << 17) | ((128u / 16) << 24);

// ===========================================================================
// prep_w: fp32 weight -> bf16 hi/lo
// ===========================================================================
__global__ __launch_bounds__(256) void prep_w(const float* __restrict__ w,
                                              size_t hiOff, size_t loOff, int n)
{
    __nv_bfloat16* hi = (__nv_bfloat16*)(g_scratch + hiOff);
    __nv_bfloat16* lo = (__nv_bfloat16*)(g_scratch + loOff);
    int i = blockIdx.x * 256 + threadIdx.x;
    if (i < n) {
        float x = w[i];
        __nv_bfloat16 h = __float2bfloat16(x);
        hi[i] = h;
        lo[i] = __float2bfloat16(x - __bfloat162float(h));
    }
}

// ===========================================================================
// gather_split: [B,C,H,W] fp32 -> token-major [TOK,512] bf16 hi/lo
// ===========================================================================
__global__ __launch_bounds__(256) void gather_split(const float* __restrict__ src,
                                                    size_t hiOff, size_t loOff)
{
    __shared__ float tile[32][129];
    __nv_bfloat16* dh = (__nv_bfloat16*)(g_scratch + hiOff);
    __nv_bfloat16* dl = (__nv_bfloat16*)(g_scratch + loOff);
    int bh = blockIdx.y;
    int b = bh >> 7, h = bh & 127;
    int c0 = blockIdx.x << 5;
    int tid = threadIdx.x;

    const float* srow = src + ((size_t)(b * 512 + c0) * 128 + h) * 128;
#pragma unroll
    for (int it = 0; it < 16; it++) {
        int idx = tid + it * 256;
        int cc = idx >> 7, w = idx & 127;
        tile[cc][w] = srow[(size_t)cc * 16384 + w];
    }
    __syncthreads();
    int r1 = h >> 3, i = h & 7;
#pragma unroll
    for (int it = 0; it < 16; it++) {
        int idx = tid + it * 256;
        int w = idx >> 5, cc = idx & 31;
        int r2 = w >> 3, j = w & 7;
        int t = ((b * 256 + r1 * 16 + r2) << 6) + i * 8 + j;
        float x = tile[cc][w];
        __nv_bfloat16 hv = __float2bfloat16(x);
        size_t o = (size_t)t * 512 + c0 + cc;
        dh[o] = hv;
        dl[o] = __float2bfloat16(x - __bfloat162float(hv));
    }
}

// ===========================================================================
// scatter: token-major fp32 [TOK,512] -> [B,C,H,W]
// ===========================================================================
__global__ __launch_bounds__(256) void scatter_win(float* __restrict__ dst)
{
    __shared__ float tile[32][129];
    const float* srcw = (const float*)(g_scratch + OFF_OW);
    int bh = blockIdx.y;
    int b = bh >> 7, h = bh & 127;
    int c0 = blockIdx.x << 5;
    int tid = threadIdx.x;
    int r1 = h >> 3, i = h & 7;

#pragma unroll
    for (int it = 0; it < 16; it++) {
        int idx = tid + it * 256;
        int w = idx >> 5, cc = idx & 31;
        int r2 = w >> 3, j = w & 7;
        int t = ((b * 256 + r1 * 16 + r2) << 6) + i * 8 + j;
        tile[cc][w] = srcw[(size_t)t * 512 + c0 + cc];
    }
    __syncthreads();
    float* drow = dst + ((size_t)(b * 512 + c0) * 128 + h) * 128;
#pragma unroll
    for (int it = 0; it < 16; it++) {
        int idx = tid + it * 256;
        int cc = idx >> 7, w = idx & 127;
        drow[(size_t)cc * 16384 + w] = tile[cc][w];
    }
}

// ===========================================================================
// gemm_bf16x3: C[M,No] = (Ahl[M,512] x Bhl[No,512]^T + bias) * scale
//   Tile 256x256, BK=32 (SW64 64B rows), depth-3 pipeline.
//   bf16 2-term split: Ah*Bh + Al*Bh + Ah*Bl, fp32 accumulate in TMEM.
//   TMEM D: 512 cols = 2 M-halves x 256 N.
// smem map (dynamic):
//   [0]        tmem ptr
//   [16,24,32] mbar[3]
//   [1024 + b*65536] buf b: Ah 16K | Al 16K | Bh 16K | Bl 16K   (b=0..2)
//   epilogue stage (fp32 128x260 = 133120B) aliases buffers at [1024]
// ===========================================================================
#define GEMM_SMEM 197632

__global__ __launch_bounds__(256) void gemm_bf16x3(
    size_t ahOff, size_t alOff, size_t bhOff, size_t blOff,
    const float* __restrict__ bias, size_t cOff, int No, float scale)
{
    extern __shared__ char smem[];
    const __nv_bfloat16* Ah = (const __nv_bfloat16*)(g_scratch + ahOff);
    const __nv_bfloat16* Al = (const __nv_bfloat16*)(g_scratch + alOff);
    const __nv_bfloat16* Bh = (const __nv_bfloat16*)(g_scratch + bhOff);
    const __nv_bfloat16* Bl = (const __nv_bfloat16*)(g_scratch + blOff);
    float* C = (float*)(g_scratch + cOff);

    int tid = threadIdx.x, wid = tid >> 5, lid = tid & 31;
    int n0 = blockIdx.x * 256, m0 = blockIdx.y * 256;

#if HAS_TCGEN05
    uint32_t sbase = smem_u32(smem);

    if (wid == 0) TCGEN05_ALLOC(sbase, 512);
    __syncthreads();
    uint32_t tmem;
    asm volatile("ld.shared.b32 %0, [%1];" : "=r"(tmem) : "r"(sbase));
    if (tid == 0) {
        MBARRIER_INIT(sbase + 16, 1);
        MBARRIER_INIT(sbase + 24, 1);
        MBARRIER_INIT(sbase + 32, 1);
    }
    __syncthreads();

    for (int kb = 0; kb < 16; kb++) {
        int buf = kb % 3;
        uint32_t bo = 1024u + (uint32_t)buf * 65536u;
        if (kb >= 3) {
            int j = kb / 3;              // commits consumed so far on this mbar
            MBARRIER_WAIT_PARITY(sbase + 16 + 8 * buf, (j - 1) & 1);
        }

        int k0 = kb * 32;
        // A tiles: 256 rows x 32 bf16 (64B rows, SW64), hi+lo: 16KB each
        const uint4* gAh = (const uint4*)(Ah + (size_t)m0 * 512 + k0);
        const uint4* gAl = (const uint4*)(Al + (size_t)m0 * 512 + k0);
        // B tiles: 256 rows x 32 bf16, hi+lo: 16KB each
        const uint4* gBh = (const uint4*)(Bh + (size_t)n0 * 512 + k0);
        const uint4* gBl = (const uint4*)(Bl + (size_t)n0 * 512 + k0);
#pragma unroll
        for (int t = 0; t < 4; t++) {
            int idx = tid + t * 256;
            int r = idx >> 2, c = idx & 3;          // row 0..255, 16B-chunk 0..3
            uint32_t so = sw64((uint32_t)(r * 64 + c * 16));
            size_t ge = (size_t)r * 64 + c;          // uint4 units: row stride 512*2B/16 = 64
            *(uint4*)(smem + bo + so)          = gAh[ge];
            *(uint4*)(smem + bo + 16384 + so)  = gAl[ge];
            *(uint4*)(smem + bo + 32768 + so)  = gBh[ge];
            *(uint4*)(smem + bo + 49152 + so)  = gBl[ge];
        }
        __syncthreads();

        if (wid == 0) {
            FENCE_ASYNC_SHARED();
            if (elect_one()) {
                uint64_t dA[2] = { MAKE_SMEM_DESC64(sbase + bo),
                                   MAKE_SMEM_DESC64(sbase + bo + 16384) };
                uint64_t dB[2] = { MAKE_SMEM_DESC64(sbase + bo + 32768),
                                   MAKE_SMEM_DESC64(sbase + bo + 49152) };
                const int pa[3] = {0, 1, 0}, pb[3] = {0, 0, 1};
#pragma unroll
                for (int p = 0; p < 3; p++) {
                    uint64_t ad = dA[pa[p]], bd = dB[pb[p]];
#pragma unroll
                    for (int ks = 0; ks < 2; ks++) {     // K=16 per step, 2 steps
                        uint32_t en = !(kb == 0 && p == 0 && ks == 0);
#pragma unroll
                        for (int mh = 0; mh < 2; mh++) { // M-halves: rows +128 = +8KB = +512 units
                            uint64_t adm = ad + mh * 512 + ks * 2;
                            mma_bf16_ss(tmem + mh * 256,       adm, bd + ks * 2,       GEMM_IDESC, en);
                            mma_bf16_ss(tmem + mh * 256 + 128, adm, bd + 512 + ks * 2, GEMM_IDESC, en);
                        }
                    }
                }
                TCGEN05_COMMIT(sbase + 16 + 8 * buf);
            }
        }
    }

    // kb=15 commit lands on mbar[0] as its 6th completion; in-loop waits on
    // mbar[0] consumed parities 0,1,0,1,0 (completions 1-5) -> wait parity 1.
    MBARRIER_WAIT_PARITY(sbase + 16, 1);
    TCGEN05_FENCE_AFTER();

    // ---- epilogue: two M-halves, TMEM -> smem stage -> gmem ----
    float* stage = (float*)(smem + 1024);
#pragma unroll 1
    for (int mh = 0; mh < 2; mh++) {
        {
            int sp = wid & 3;             // subpartition rows sp*32 + lid
            int cbase = (wid >> 2) * 128; // warps 0-3: cols 0-127, 4-7: 128-255
#pragma unroll
            for (int cc = 0; cc < 128; cc += 32) {
                uint32_t r[32];
                TCGEN05_LD_X32(r, tmem + mh * 256 + cbase + cc);
                TCGEN05_WAIT_LD();
                float* row = stage + (size_t)(sp * 32 + lid) * 260 + cbase + cc;
#pragma unroll
                for (int i = 0; i < 8; i++) {
                    float4 v = make_float4(__uint_as_float(r[4 * i]), __uint_as_float(r[4 * i + 1]),
                                           __uint_as_float(r[4 * i + 2]), __uint_as_float(r[4 * i + 3]));
                    *(float4*)(row + 4 * i) = v;
                }
            }
        }
        TCGEN05_FENCE_BEFORE();
        __syncthreads();

#pragma unroll
        for (int t = 0; t < 32; t++) {
            int j = tid + t * 256;        // float4 index in 128x256 chunk
            int r = j >> 6, c4 = j & 63;
            float4 v = *(float4*)(stage + (size_t)r * 260 + c4 * 4);
            float4 b = *(const float4*)(bias + n0 + c4 * 4);
            float4 o;
            o.x = (v.x + b.x) * scale;
            o.y = (v.y + b.y) * scale;
            o.z = (v.z + b.z) * scale;
            o.w = (v.w + b.w) * scale;
            *(float4*)(C + (size_t)(m0 + mh * 128 + r) * No + n0 + c4 * 4) = o;
        }
        __syncthreads();   // stage reused by next mh
    }

    if (tid == 0) {
        MBARRIER_INVAL(sbase + 16);
        MBARRIER_INVAL(sbase + 24);
        MBARRIER_INVAL(sbase + 32);
    }
    __syncthreads();
    if (wid == 0) { TCGEN05_RELINQ(); TCGEN05_DEALLOC(tmem, 512); }

#else  // ---- FFMA fallback for the plain compute_103 pass ----
    float* As = (float*)smem;                  // [16][128]
    float* Bs = (float*)(smem + 16 * 128 * 4); // [16][64]
    int tx = tid & 15, ty = tid >> 4;

    for (int msub = 0; msub < 2; msub++) {
        int m0c = m0 + msub * 128;
        for (int nsub = 0; nsub < 4; nsub++) {
            int nc0 = n0 + nsub * 64;
            float acc[8][4];
#pragma unroll
            for (int u = 0; u < 8; u++)
#pragma unroll
                for (int v = 0; v < 4; v++) acc[u][v] = 0.f;

            for (int k0 = 0; k0 < 512; k0 += 16) {
#pragma unroll
                for (int t = 0; t < 8; t++) {
                    int e = tid + t * 256;
                    int r = e & 127, kk = e >> 7;
                    size_t g = (size_t)(m0c + r) * 512 + k0 + kk;
                    As[kk * 128 + r] = __bfloat162float(Ah[g]) + __bfloat162float(Al[g]);
                }
#pragma unroll
                for (int t = 0; t < 4; t++) {
                    int e = tid + t * 256;
                    int r = e & 63, kk = e >> 6;
                    size_t g = (size_t)(nc0 + r) * 512 + k0 + kk;
                    Bs[kk * 64 + r] = __bfloat162float(Bh[g]) + __bfloat162float(Bl[g]);
                }
                __syncthreads();
#pragma unroll
                for (int kk = 0; kk < 16; kk++) {
                    float a[8], b[4];
#pragma unroll
                    for (int u = 0; u < 8; u++) a[u] = As[kk * 128 + ty * 8 + u];
#pragma unroll
                    for (int v = 0; v < 4; v++) b[v] = Bs[kk * 64 + tx * 4 + v];
#pragma unroll
                    for (int u = 0; u < 8; u++)
#pragma unroll
                        for (int v = 0; v < 4; v++) acc[u][v] += a[u] * b[v];
                }
                __syncthreads();
            }

#pragma unroll
            for (int u = 0; u < 8; u++)
#pragma unroll
                for (int v = 0; v < 4; v++)
                    C[(size_t)(m0c + ty * 8 + u) * No + nc0 + tx * 4 + v] =
                        (acc[u][v] + bias[nc0 + tx * 4 + v]) * scale;
            __syncthreads();
        }
    }
#endif
}

// ===========================================================================
// attention: one block per (window, head); Q/KV fp32 in, AO bf16 hi/lo out
// ===========================================================================
__global__ __launch_bounds__(256) void attn_kernel(const float* __restrict__ rpb,
                                                   const int* __restrict__ relidx)
{
    __shared__ float qs[64][33];
    __shared__ float ks[64][33];
    __shared__ float vs[64][33];
    __shared__ float ps[64][68];

    const float* Q  = (const float*)(g_scratch + OFF_Q);
    const float* KV = (const float*)(g_scratch + OFF_KV);
    __nv_bfloat16* AOh = (__nv_bfloat16*)(g_scratch + OFF_AOH);
    __nv_bfloat16* AOl = (__nv_bfloat16*)(g_scratch + OFF_AOL);

    int m = blockIdx.x;
    int h = blockIdx.y;
    int tid = threadIdx.x;
    size_t tb = (size_t)m * 64;

#pragma unroll
    for (int it = 0; it < 8; it++) {
        int idx = tid + it * 256;
        int n = idx >> 5, d = idx & 31;
        qs[n][d] = Q[(tb + n) * 512 + h * 32 + d];
        ks[n][d] = KV[(tb + n) * 1024 + h * 32 + d];
        vs[n][d] = KV[(tb + n) * 1024 + 512 + h * 32 + d];
    }
    __syncthreads();

    {
        int tx = tid & 15, ty = tid >> 4;
        float s[4][4];
#pragma unroll
        for (int u = 0; u < 4; u++)
#pragma unroll
            for (int v = 0; v < 4; v++) s[u][v] = 0.f;
#pragma unroll
        for (int d = 0; d < 32; d++) {
            float a[4], b[4];
#pragma unroll
            for (int u = 0; u < 4; u++) a[u] = qs[ty * 4 + u][d];
#pragma unroll
            for (int v = 0; v < 4; v++) b[v] = ks[tx * 4 + v][d];
#pragma unroll
            for (int u = 0; u < 4; u++)
#pragma unroll
                for (int v = 0; v < 4; v++) s[u][v] += a[u] * b[v];
        }
#pragma unroll
        for (int u = 0; u < 4; u++)
#pragma unroll
            for (int v = 0; v < 4; v++) {
                int mq = ty * 4 + u, nk = tx * 4 + v;
                int ri = relidx[mq * 64 + nk];
                ps[mq][nk] = s[u][v] + rpb[ri * NHEADS + h];
            }
    }
    __syncthreads();

    {
        int g = tid & 3, row = tid >> 2;
        float mx = -1e30f;
        for (int c = g; c < 64; c += 4) mx = fmaxf(mx, ps[row][c]);
        mx = fmaxf(mx, __shfl_xor_sync(0xffffffffu, mx, 1));
        mx = fmaxf(mx, __shfl_xor_sync(0xffffffffu, mx, 2));
        float sum = 0.f;
        for (int c = g; c < 64; c += 4) {
            float e = __expf(ps[row][c] - mx);
            ps[row][c] = e;
            sum += e;
        }
        sum += __shfl_xor_sync(0xffffffffu, sum, 1);
        sum += __shfl_xor_sync(0xffffffffu, sum, 2);
        float inv = 1.f / sum;
        for (int c = g; c < 64; c += 4) ps[row][c] *= inv;
    }
    __syncthreads();

    {
        int tx = tid & 7, ty = tid >> 3;
        float acc[2][4];
#pragma unroll
        for (int u = 0; u < 2; u++)
#pragma unroll
            for (int v = 0; v < 4; v++) acc[u][v] = 0.f;
#pragma unroll
        for (int nk = 0; nk < 64; nk++) {
            float p0 = ps[ty * 2 + 0][nk];
            float p1 = ps[ty * 2 + 1][nk];
#pragma unroll
            for (int v = 0; v < 4; v++) {
                float vv = vs[nk][tx * 4 + v];
                acc[0][v] += p0 * vv;
                acc[1][v] += p1 * vv;
            }
        }
#pragma unroll
        for (int u = 0; u < 2; u++) {
            size_t o = (tb + ty * 2 + u) * 512 + h * 32 + tx * 4;
            unsigned short hh[4], ll[4];
#pragma unroll
            for (int v = 0; v < 4; v++) {
                float x = acc[u][v];
                __nv_bfloat16 hv = __float2bfloat16(x);
                __nv_bfloat16 lv = __float2bfloat16(x - __bfloat162float(hv));
                hh[v] = *(unsigned short*)&hv;
                ll[v] = *(unsigned short*)&lv;
            }
            uint2 ph = make_uint2((uint32_t)hh[0] | ((uint32_t)hh[1] << 16),
                                  (uint32_t)hh[2] | ((uint32_t)hh[3] << 16));
            uint2 pl = make_uint2((uint32_t)ll[0] | ((uint32_t)ll[1] << 16),
                                  (uint32_t)ll[2] | ((uint32_t)ll[3] << 16));
            *(uint2*)(AOh + o) = ph;
            *(uint2*)(AOl + o) = pl;
        }
    }
}

// ===========================================================================
extern "C" void kernel_launch(void* const* d_in, const int* in_sizes, int n_in,
                              void* d_out, int out_size)
{
    const float* xa     = (const float*)d_in[0];
    const float* xb     = (const float*)d_in[1];
    const float* Wq     = (const float*)d_in[2];
    const float* bq     = (const float*)d_in[3];
    const float* Wkv    = (const float*)d_in[4];
    const float* bkv    = (const float*)d_in[5];
    const float* Wo     = (const float*)d_in[6];
    const float* bo     = (const float*)d_in[7];
    const float* rpb    = (const float*)d_in[8];
    const int*   relidx = (const int*)d_in[9];
    float* out = (float*)d_out;

    const float scale = 0.17677669529663687f; // 32^-0.5

    // idempotent, non-enqueuing, capture-safe
    cudaFuncSetAttribute(gemm_bf16x3, cudaFuncAttributeMaxDynamicSharedMemorySize, GEMM_SMEM);

    dim3 gwin(16, 1024);
    // Order chosen so gemmQ is the 5th launch (ncu -s 5 -c 1 profiles it).
    gather_split<<<gwin, 256>>>(xa, OFF_XAH, OFF_XAL);                    // 1
    gather_split<<<gwin, 256>>>(xb, OFF_XBH, OFF_XBL);                    // 2
    prep_w<<<1024, 256>>>(Wq,  OFF_WQH,  OFF_WQL,  512 * 512);            // 3
    prep_w<<<2048, 256>>>(Wkv, OFF_WKVH, OFF_WKVL, 1024 * 512);           // 4

    gemm_bf16x3<<<dim3(2, 512), 256, GEMM_SMEM>>>(OFF_XAH, OFF_XAL,       // 5
                                                  OFF_WQH, OFF_WQL,
                                                  bq, OFF_Q, 512, scale);

    prep_w<<<1024, 256>>>(Wo,  OFF_WOH,  OFF_WOL,  512 * 512);            // 6

    gemm_bf16x3<<<dim3(4, 512), 256, GEMM_SMEM>>>(OFF_XBH, OFF_XBL,       // 7
                                                  OFF_WKVH, OFF_WKVL,
                                                  bkv, OFF_KV, 1024, 1.0f);

    attn_kernel<<<dim3(NWIN, NHEADS), 256>>>(rpb, relidx);                // 8

    gemm_bf16x3<<<dim3(2, 512), 256, GEMM_SMEM>>>(OFF_AOH, OFF_AOL,       // 9
                                                  OFF_WOH, OFF_WOL,
                                                  bo, OFF_OW, 512, 1.0f);

    scatter_win<<<gwin, 256>>>(out);                                      // 10
}